// round 5
// baseline (speedup 1.0000x reference)
#include <cuda_runtime.h>
#include <math.h>
#include <stdint.h>

#define BB 4
#define TT 2048
#define CC 1024
#define HH 64
#define NROWS (BB * TT)   // 8192

__device__ float g_q[NROWS * HH];
__device__ float g_k[NROWS * HH];
__device__ float g_v[NROWS * HH];

typedef unsigned long long ull;

// ---------------- f32x2 helpers ----------------
__device__ __forceinline__ void ffma2(ull& d, ull a, ull b) {
    asm("fma.rn.f32x2 %0, %1, %2, %0;" : "+l"(d) : "l"(a), "l"(b));
}
__device__ __forceinline__ void fmul2(ull& d, ull a) {
    asm("mul.rn.f32x2 %0, %0, %1;" : "+l"(d) : "l"(a));
}
__device__ __forceinline__ ull pack2(float lo, float hi) {
    ull r; asm("mov.b64 %0, {%1, %2};" : "=l"(r) : "f"(lo), "f"(hi)); return r;
}
__device__ __forceinline__ void unpack2(ull v, float& a, float& b) {
    asm("mov.b64 {%0, %1}, %2;" : "=f"(a), "=f"(b) : "l"(v));
}
__device__ __forceinline__ void lds_2x64(ull& a, ull& b, const void* p) {
    uint32_t sa = (uint32_t)__cvta_generic_to_shared(p);
    asm volatile("ld.shared.v2.u64 {%0, %1}, [%2];" : "=l"(a), "=l"(b) : "r"(sa));
}
__device__ __forceinline__ void cp_async16(void* smem_dst, const void* gptr) {
    uint32_t sa = (uint32_t)__cvta_generic_to_shared(smem_dst);
    asm volatile("cp.async.cg.shared.global [%0], [%1], 16;" :: "r"(sa), "l"(gptr));
}
#define CP_COMMIT() asm volatile("cp.async.commit_group;")
#define CP_WAIT(n)  asm volatile("cp.async.wait_group %0;" :: "n"(n))

// ---------------------------------------------------------------------------
// Kernel 1: QKV projection. BM=64, BN=64, BK=32, 128 threads.
// Thread tile 8m x 4n, m-PAIR-packed accumulators (A gives natural ull pairs
// from As[k][m]; A reads are 16-lane broadcasts -> almost no crossbar cost).
// A: LDG->regs->STS (transposed, stride 68). B: cp.async natural [k][n].
// grid = (128, 3) = 384 blocks.
// ---------------------------------------------------------------------------
__global__ __launch_bounds__(128) void proj_kernel(
    const float* __restrict__ x,
    const float* __restrict__ Wq,
    const float* __restrict__ Wk,
    const float* __restrict__ Wv)
{
    const float* W = (blockIdx.y == 0) ? Wq : (blockIdx.y == 1) ? Wk : Wv;
    float* out     = (blockIdx.y == 0) ? g_q : (blockIdx.y == 1) ? g_k : g_v;

    __shared__ float As[2][32][68];   // [buf][k][m], stride 68 (16B-aligned rows)
    __shared__ float Bs[2][32][64];   // [buf][k][n]

    const int tid  = threadIdx.x;
    const int tm   = tid >> 4;        // 0..7  -> m0 = tm*8
    const int tn   = tid & 15;        // 0..15 -> n0 = tn*4
    const int row0 = blockIdx.x * 64;

    // A load lanes: 4 float4 chunks
    int arow[4], akc[4];
#pragma unroll
    for (int s = 0; s < 4; s++) {
        const int ch = tid + s * 128;     // 0..511
        arow[s] = ch >> 3;                // 0..63
        akc[s]  = ch & 7;                 // 0..7
    }
    // B load lanes: 4 cp.async chunks
    ull acc[4][4] = {};
    float4 ar[4];

    // prologue
#pragma unroll
    for (int s = 0; s < 4; s++)
        ar[s] = *(const float4*)&x[(row0 + arow[s]) * CC + akc[s] * 4];
#pragma unroll
    for (int s = 0; s < 4; s++) {
        const int ch = tid + s * 128;
        const int k = ch >> 4, nc = ch & 15;
        cp_async16(&Bs[0][k][nc * 4], &W[k * HH + nc * 4]);
    }
    CP_COMMIT();
#pragma unroll
    for (int s = 0; s < 4; s++) {
        As[0][akc[s] * 4 + 0][arow[s]] = ar[s].x;
        As[0][akc[s] * 4 + 1][arow[s]] = ar[s].y;
        As[0][akc[s] * 4 + 2][arow[s]] = ar[s].z;
        As[0][akc[s] * 4 + 3][arow[s]] = ar[s].w;
    }
#pragma unroll
    for (int s = 0; s < 4; s++)
        ar[s] = *(const float4*)&x[(row0 + arow[s]) * CC + 32 + akc[s] * 4];
    CP_WAIT(0);
    __syncthreads();

    for (int t = 0; t < 32; t++) {
        const int buf = t & 1;
        if (t < 31) {
            const int k0n = (t + 1) * 32;
#pragma unroll
            for (int s = 0; s < 4; s++) {
                const int ch = tid + s * 128;
                const int k = ch >> 4, nc = ch & 15;
                cp_async16(&Bs[buf ^ 1][k][nc * 4], &W[(k0n + k) * HH + nc * 4]);
            }
            CP_COMMIT();
#pragma unroll
            for (int s = 0; s < 4; s++) {
                As[buf ^ 1][akc[s] * 4 + 0][arow[s]] = ar[s].x;
                As[buf ^ 1][akc[s] * 4 + 1][arow[s]] = ar[s].y;
                As[buf ^ 1][akc[s] * 4 + 2][arow[s]] = ar[s].z;
                As[buf ^ 1][akc[s] * 4 + 3][arow[s]] = ar[s].w;
            }
        }

#pragma unroll 16
        for (int k = 0; k < 32; k++) {
            ull a01, a23, a45, a67;
            lds_2x64(a01, a23, &As[buf][k][tm * 8]);
            lds_2x64(a45, a67, &As[buf][k][tm * 8 + 4]);
            float4 b4 = *(const float4*)&Bs[buf][k][tn * 4];
            const ull b0 = pack2(b4.x, b4.x);
            const ull b1 = pack2(b4.y, b4.y);
            const ull b2 = pack2(b4.z, b4.z);
            const ull b3 = pack2(b4.w, b4.w);
            ffma2(acc[0][0], a01, b0); ffma2(acc[0][1], a01, b1);
            ffma2(acc[0][2], a01, b2); ffma2(acc[0][3], a01, b3);
            ffma2(acc[1][0], a23, b0); ffma2(acc[1][1], a23, b1);
            ffma2(acc[1][2], a23, b2); ffma2(acc[1][3], a23, b3);
            ffma2(acc[2][0], a45, b0); ffma2(acc[2][1], a45, b1);
            ffma2(acc[2][2], a45, b2); ffma2(acc[2][3], a45, b3);
            ffma2(acc[3][0], a67, b0); ffma2(acc[3][1], a67, b1);
            ffma2(acc[3][2], a67, b2); ffma2(acc[3][3], a67, b3);
        }

        if (t < 31) {
            if (t < 30) {
                const int k0nn = (t + 2) * 32;
#pragma unroll
                for (int s = 0; s < 4; s++)
                    ar[s] = *(const float4*)&x[(row0 + arow[s]) * CC + k0nn + akc[s] * 4];
            }
            CP_WAIT(0);
            __syncthreads();
        }
    }

    // epilogue: acc[mp][n] = {rows 2mp, 2mp+1}
#pragma unroll
    for (int mp = 0; mp < 4; mp++) {
        float lo0, hi0, lo1, hi1, lo2, hi2, lo3, hi3;
        unpack2(acc[mp][0], lo0, hi0);
        unpack2(acc[mp][1], lo1, hi1);
        unpack2(acc[mp][2], lo2, hi2);
        unpack2(acc[mp][3], lo3, hi3);
        float* r0 = &out[(row0 + tm * 8 + 2 * mp) * HH + tn * 4];
        float* r1 = &out[(row0 + tm * 8 + 2 * mp + 1) * HH + tn * 4];
        *(float4*)r0 = make_float4(lo0, lo1, lo2, lo3);
        *(float4*)r1 = make_float4(hi0, hi1, hi2, hi3);
    }
}

// ---------------------------------------------------------------------------
// Kernel 2: causal attention. 128 threads (4 warps), QT=32 rows per block,
// 8 rows per warp (doubles FFMA2 per smem byte). Lane l: cols/dims {l, l+32}.
// PV uses j-pair f32x2 with transposed Vt[dim][j] + Pw[i][j] (no pack movs).
// K via cp.async (double buffered, XOR swizzled); V via LDG->regs->STS into
// Vt (XOR swizzled). LPT: qt = 63 - bx (heaviest first). grid (64, 4).
// smem 80KB dynamic -> 2 blocks/SM.
// ---------------------------------------------------------------------------
#define SM_KS(buf)  (sm + (buf) * 4096)            // [64][64] swizzled
#define SM_VT(buf)  (sm + 8192 + (buf) * 4096)     // [dim][j] swizzled
#define SM_Q        (sm + 16384)                   // [32][64]
#define SM_PW       (sm + 18432)                   // [4][8][64]
#define ATTN_SMEM_BYTES ((18432 + 2048) * 4)       // 81920 B = 80KB

__global__ __launch_bounds__(128) void attn_kernel(float* __restrict__ out)
{
    extern __shared__ float sm[];

    const int b   = blockIdx.y;
    const int qt  = 63 - blockIdx.x;      // LPT: heavy first
    const int qs  = qt * 32;
    const int tid = threadIdx.x;
    const int w   = tid >> 5;
    const int l   = tid & 31;

    const float* qb = g_q + b * TT * HH;
    const float* kb = g_k + b * TT * HH;
    const float* vb = g_v + b * TT * HH;
    float*       ob = out + b * TT * HH;

    float* pw = SM_PW + (w << 9);         // [8][64]

    // fill lane mappings (16B chunks over a 64x64 tile)
    int frow[8], fc4[8];
#pragma unroll
    for (int s = 0; s < 8; s++) {
        const int ch = tid + s * 128;     // 0..1023
        frow[s] = ch >> 4;
        fc4[s]  = ch & 15;
    }

    const int nkb = (qs + 32 + 63) >> 6;

    // ---- prologue: Q + K0 via cp.async, V0 via LDG ----
#pragma unroll
    for (int s = 0; s < 4; s++) {
        const int ch = tid + s * 128;     // 0..511
        cp_async16(SM_Q + ch * 4, &qb[qs * 64 + ch * 4]);
    }
#pragma unroll
    for (int s = 0; s < 8; s++)
        cp_async16(SM_KS(0) + frow[s] * 64 + ((fc4[s] ^ (frow[s] & 7)) << 2),
                   &kb[frow[s] * 64 + fc4[s] * 4]);
    float4 vr[8];
#pragma unroll
    for (int s = 0; s < 8; s++)
        vr[s] = *(const float4*)&vb[frow[s] * 64 + fc4[s] * 4];
    CP_COMMIT();
    CP_WAIT(0);
    __syncthreads();
    // transpose V0 into Vt[0]
#pragma unroll
    for (int s = 0; s < 8; s++) {
        const int j = frow[s];
        float vv[4] = {vr[s].x, vr[s].y, vr[s].z, vr[s].w};
#pragma unroll
        for (int e = 0; e < 4; e++) {
            const int d = fc4[s] * 4 + e;
            SM_VT(0)[d * 64 + (((j >> 2) ^ (d & 15)) << 2) + (j & 3)] = vv[e];
        }
    }
    __syncthreads();

    float m[8], lsum[8];
    ull accL[8], accH[8];
#pragma unroll
    for (int i = 0; i < 8; i++) {
        m[i] = -INFINITY; lsum[i] = 0.f; accL[i] = 0ull; accH[i] = 0ull;
    }

    for (int t = 0; t < nkb; t++) {
        const int buf = t & 1;
        if (t + 1 < nkb) {
            const float* kn = &kb[(t + 1) * 64 * 64];
            const float* vn = &vb[(t + 1) * 64 * 64];
#pragma unroll
            for (int s = 0; s < 8; s++)
                cp_async16(SM_KS(buf ^ 1) + frow[s] * 64 + ((fc4[s] ^ (frow[s] & 7)) << 2),
                           kn + frow[s] * 64 + fc4[s] * 4);
            CP_COMMIT();
#pragma unroll
            for (int s = 0; s < 8; s++)
                vr[s] = *(const float4*)&vn[frow[s] * 64 + fc4[s] * 4];
        }

        const float* Ks = SM_KS(buf);
        const float* Vt = SM_VT(buf);

        // ---- scores: 8 rows, k-packed ----
        ull s2[8][2] = {};
#pragma unroll
        for (int c4 = 0; c4 < 16; c4++) {
            ull kl0, kl1, kh0, kh1;
            lds_2x64(kl0, kl1, &Ks[l * 64 + ((c4 ^ (l & 7)) << 2)]);
            lds_2x64(kh0, kh1, &Ks[(l + 32) * 64 + ((c4 ^ (l & 7)) << 2)]);
#pragma unroll
            for (int i = 0; i < 8; i++) {
                ull q0, q1;
                lds_2x64(q0, q1, &SM_Q[((w << 3) + i) * 64 + c4 * 4]);
                ffma2(s2[i][0], q0, kl0); ffma2(s2[i][0], q1, kl1);
                ffma2(s2[i][1], q0, kh0); ffma2(s2[i][1], q1, kh1);
            }
        }

        // ---- online softmax (exact reference mask: col>row || s==0 -> -inf)
        const int col0 = t * 64 + l;
        const int col1 = col0 + 32;
#pragma unroll
        for (int i = 0; i < 8; i++) {
            const int rowg = qs + (w << 3) + i;
            float lo, hi, sc0, sc1;
            unpack2(s2[i][0], lo, hi);  sc0 = (lo + hi) * 0.125f;
            unpack2(s2[i][1], lo, hi);  sc1 = (lo + hi) * 0.125f;
            if (col0 > rowg || sc0 == 0.0f) sc0 = -INFINITY;
            if (col1 > rowg || sc1 == 0.0f) sc1 = -INFINITY;

            float rmax = fmaxf(sc0, sc1);
#pragma unroll
            for (int off = 16; off > 0; off >>= 1)
                rmax = fmaxf(rmax, __shfl_xor_sync(0xffffffffu, rmax, off));

            const float mnew = fmaxf(m[i], rmax);
            const float f    = __expf(m[i] - mnew);
            const float p0   = __expf(sc0 - mnew);
            const float p1   = __expf(sc1 - mnew);

            float psum = p0 + p1;
#pragma unroll
            for (int off = 16; off > 0; off >>= 1)
                psum += __shfl_xor_sync(0xffffffffu, psum, off);

            lsum[i] = lsum[i] * f + psum;
            m[i] = mnew;
            const ull f2 = pack2(f, f);
            fmul2(accL[i], f2);
            fmul2(accH[i], f2);
            pw[i * 64 + l]      = p0;
            pw[i * 64 + l + 32] = p1;
        }
        __syncwarp();

        // ---- P @ V: j-pair packed, zero pack movs ----
#pragma unroll 4
        for (int jq = 0; jq < 16; jq++) {
            ull vl0, vl1, vh0, vh1;
            lds_2x64(vl0, vl1, &Vt[l * 64 + ((jq ^ (l & 15)) << 2)]);
            lds_2x64(vh0, vh1, &Vt[(l + 32) * 64 + ((jq ^ (l & 15)) << 2)]);
#pragma unroll
            for (int i = 0; i < 8; i++) {
                ull p0, p1;
                lds_2x64(p0, p1, &pw[i * 64 + jq * 4]);   // broadcast
                ffma2(accL[i], p0, vl0); ffma2(accL[i], p1, vl1);
                ffma2(accH[i], p0, vh0); ffma2(accH[i], p1, vh1);
            }
        }
        __syncthreads();   // all warps done with Ks[buf], Vt[buf]

        if (t + 1 < nkb) {
#pragma unroll
            for (int s = 0; s < 8; s++) {
                const int j = frow[s];
                float vv[4] = {vr[s].x, vr[s].y, vr[s].z, vr[s].w};
#pragma unroll
                for (int e = 0; e < 4; e++) {
                    const int d = fc4[s] * 4 + e;
                    SM_VT(buf ^ 1)[d * 64 + (((j >> 2) ^ (d & 15)) << 2) + (j & 3)] = vv[e];
                }
            }
            CP_WAIT(0);
            __syncthreads();   // next tile ready
        }
    }

    // ---- epilogue: horizontal add of j-pair halves ----
#pragma unroll
    for (int i = 0; i < 8; i++) {
        const int rowg = qs + (w << 3) + i;
        const float inv = 1.0f / lsum[i];
        float lo, hi;
        unpack2(accL[i], lo, hi);
        ob[rowg * HH + l] = (lo + hi) * inv;
        unpack2(accH[i], lo, hi);
        ob[rowg * HH + l + 32] = (lo + hi) * inv;
    }
}

// ---------------------------------------------------------------------------
extern "C" void kernel_launch(void* const* d_in, const int* in_sizes, int n_in,
                              void* d_out, int out_size)
{
    const float* x  = (const float*)d_in[0];
    const float* Wq = (const float*)d_in[1];
    const float* Wk = (const float*)d_in[2];
    const float* Wv = (const float*)d_in[3];
    float* out = (float*)d_out;

    static int smem_set = 0;
    if (!smem_set) {
        cudaFuncSetAttribute(attn_kernel,
                             cudaFuncAttributeMaxDynamicSharedMemorySize,
                             ATTN_SMEM_BYTES);
        smem_set = 1;
    }

    proj_kernel<<<dim3(NROWS / 64, 3), 128>>>(x, Wq, Wk, Wv);
    attn_kernel<<<dim3(64, BB), 128, ATTN_SMEM_BYTES>>>(out);
}